// round 6
// baseline (speedup 1.0000x reference)
#include <cuda_runtime.h>
#include <cuda_bf16.h>
#include <cstdint>

// Problem constants
#define T_STEPS 512
#define BATCH   256
#define D_IN    512
#define HID     128
#define G4      512   // 4*H
#define YS_ELEMS (T_STEPS * BATCH * HID)
#define M_TOTAL  (T_STEPS * BATCH)        // 131072

typedef unsigned long long ull;

// ---------------- device scratch (static; allowed) ----------------
__device__ float          g_xpre [(size_t)M_TOTAL * G4];       // 256 MB
__device__ __nv_bfloat16  g_obs_hi[(size_t)M_TOTAL * D_IN];    // 128 MB
__device__ __nv_bfloat16  g_obs_lo[(size_t)M_TOTAL * D_IN];    // 128 MB
__device__ __nv_bfloat16  g_wiT_hi[(size_t)G4 * D_IN];         // [n][k]
__device__ __nv_bfloat16  g_wiT_lo[(size_t)G4 * D_IN];

// ---------------- small helpers ----------------
__device__ __forceinline__ ull fpack2(float lo, float hi) {
    ull r; asm("mov.b64 %0, {%1, %2};" : "=l"(r) : "f"(lo), "f"(hi)); return r;
}
__device__ __forceinline__ ull ffma2(ull a, ull b, ull c) {
    ull d; asm("fma.rn.f32x2 %0, %1, %2, %3;" : "=l"(d) : "l"(a), "l"(b), "l"(c)); return d;
}
__device__ __forceinline__ float funpack_add(ull p) {
    float lo, hi; asm("mov.b64 {%0, %1}, %2;" : "=f"(lo), "=f"(hi) : "l"(p));
    return lo + hi;
}
__device__ __forceinline__ float sigm_(float x) {
    return __fdividef(1.0f, 1.0f + __expf(-x));
}
__device__ __forceinline__ float tanh_(float x) {
    float e = __expf(-2.0f * x);
    return __fdividef(1.0f - e, 1.0f + e);
}
__device__ __forceinline__ uint32_t smem_u32(const void* p) {
    uint32_t a;
    asm("{ .reg .u64 t; cvta.to.shared.u64 t, %1; cvt.u32.u64 %0, t; }" : "=r"(a) : "l"(p));
    return a;
}

// SW128 swizzle (byte offsets within a 128B-row tile)
#define SWZ128(o) ((o) ^ (((o) >> 3) & 0x70))

__device__ __forceinline__ void cpasync16(uint32_t s, const void* g) {
    asm volatile("cp.async.cg.shared.global [%0], [%1], 16;" :: "r"(s), "l"(g));
}
__device__ __forceinline__ void ldsm_x4(uint32_t* r, uint32_t addr) {
    asm volatile("ldmatrix.sync.aligned.m8n8.x4.shared.b16 {%0,%1,%2,%3}, [%4];"
        : "=r"(r[0]), "=r"(r[1]), "=r"(r[2]), "=r"(r[3]) : "r"(addr));
}
__device__ __forceinline__ void mma16816(float* c, const uint32_t* a, const uint32_t* b) {
    asm volatile("mma.sync.aligned.m16n8k16.row.col.f32.bf16.bf16.f32 "
        "{%0,%1,%2,%3}, {%4,%5,%6,%7}, {%8,%9}, {%0,%1,%2,%3};"
        : "+f"(c[0]), "+f"(c[1]), "+f"(c[2]), "+f"(c[3])
        : "r"(a[0]), "r"(a[1]), "r"(a[2]), "r"(a[3]), "r"(b[0]), "r"(b[1]));
}

// ============================================================
// Prep 1: split obs fp32 -> bf16 hi/lo
// ============================================================
__global__ __launch_bounds__(256)
void split_obs_kernel(const float* __restrict__ obs) {
    size_t n4 = (size_t)M_TOTAL * D_IN / 4;
    size_t stride = (size_t)gridDim.x * blockDim.x;
    for (size_t i = (size_t)blockIdx.x * blockDim.x + threadIdx.x; i < n4; i += stride) {
        float4 v = ((const float4*)obs)[i];
        __nv_bfloat16 h0 = __float2bfloat16(v.x);
        __nv_bfloat16 h1 = __float2bfloat16(v.y);
        __nv_bfloat16 h2 = __float2bfloat16(v.z);
        __nv_bfloat16 h3 = __float2bfloat16(v.w);
        __nv_bfloat16 l0 = __float2bfloat16(v.x - __bfloat162float(h0));
        __nv_bfloat16 l1 = __float2bfloat16(v.y - __bfloat162float(h1));
        __nv_bfloat16 l2 = __float2bfloat16(v.z - __bfloat162float(h2));
        __nv_bfloat16 l3 = __float2bfloat16(v.w - __bfloat162float(h3));
        ((__nv_bfloat162*)g_obs_hi)[2 * i]     = __nv_bfloat162(h0, h1);
        ((__nv_bfloat162*)g_obs_hi)[2 * i + 1] = __nv_bfloat162(h2, h3);
        ((__nv_bfloat162*)g_obs_lo)[2 * i]     = __nv_bfloat162(l0, l1);
        ((__nv_bfloat162*)g_obs_lo)[2 * i + 1] = __nv_bfloat162(l2, l3);
    }
}

// ============================================================
// Prep 2: transpose + split Wi [k][n] -> WiT hi/lo [n][k]
// ============================================================
__global__ __launch_bounds__(256)
void split_wiT_kernel(const float* __restrict__ Wi) {
    int idx = blockIdx.x * blockDim.x + threadIdx.x;
    if (idx < G4 * D_IN) {
        int n = idx >> 9, k = idx & 511;
        float v = Wi[k * G4 + n];
        __nv_bfloat16 h = __float2bfloat16(v);
        __nv_bfloat16 l = __float2bfloat16(v - __bfloat162float(h));
        g_wiT_hi[idx] = h;
        g_wiT_lo[idx] = l;
    }
}

// ============================================================
// GEMM via mma.sync bf16-split (verified, unchanged):
//   Xpre = bias + obs @ Wi  via  Ah*Bh + Ah*Bl + Al*Bh, fp32 acc
// ============================================================
#define GSTAGE 65536          // Ah 16K | Al 16K | Bh 16K | Bl 16K
#define GSM_TOTAL (2 * GSTAGE)

__global__ __launch_bounds__(256, 1)
void gemm_hmma_kernel(const float* __restrict__ bias)
{
    extern __shared__ __align__(1024) char smem[];
    const uint32_t smb = smem_u32(smem);
    const int tid = threadIdx.x;
    const int warp = tid >> 5, lane = tid & 31;
    const int bn = blockIdx.x;     // 0..3
    const int bm = blockIdx.y;     // 0..1023

    const __nv_bfloat16* Agh = g_obs_hi + (size_t)bm * 128 * 512;
    const __nv_bfloat16* Agl = g_obs_lo + (size_t)bm * 128 * 512;
    const __nv_bfloat16* Bgh = g_wiT_hi + (size_t)bn * 128 * 512;
    const __nv_bfloat16* Bgl = g_wiT_lo + (size_t)bn * 128 * 512;

    auto load_stage = [&](int kc, int s) {
        const __nv_bfloat16* srcs[4] = {Agh, Agl, Bgh, Bgl};
        uint32_t sb = smb + s * GSTAGE;
#pragma unroll
        for (int tile = 0; tile < 4; tile++) {
            const __nv_bfloat16* src = srcs[tile];
            uint32_t tb = sb + tile * 16384;
#pragma unroll
            for (int t = 0; t < 4; t++) {
                int i = tid + t * 256;
                int row = i >> 3, cc = i & 7;
                uint32_t so = tb + SWZ128((uint32_t)(row * 128 + cc * 16));
                cpasync16(so, src + (size_t)row * 512 + kc * 64 + cc * 8);
            }
        }
        asm volatile("cp.async.commit_group;" ::: "memory");
    };

    const int wm = (warp & 3) * 32;
    const int wn = (warp >> 2) * 64;
    const int lr = lane & 7, g = lane >> 3;

    float acc[2][8][4];
#pragma unroll
    for (int i = 0; i < 2; i++)
#pragma unroll
        for (int j = 0; j < 8; j++)
#pragma unroll
            for (int q = 0; q < 4; q++) acc[i][j][q] = 0.0f;

    load_stage(0, 0);

    for (int kc = 0; kc < 8; kc++) {
        if (kc + 1 < 8) {
            load_stage(kc + 1, (kc + 1) & 1);
            asm volatile("cp.async.wait_group 1;" ::: "memory");
        } else {
            asm volatile("cp.async.wait_group 0;" ::: "memory");
        }
        __syncthreads();

        uint32_t sb = smb + (kc & 1) * GSTAGE;
#pragma unroll
        for (int ks = 0; ks < 4; ks++) {
            uint32_t ah[2][4], al[2][4];
#pragma unroll
            for (int am = 0; am < 2; am++) {
                int mrow = wm + am * 16 + (g & 1) * 8 + lr;
                int kb = ks * 16 + (g >> 1) * 8;
                uint32_t off = SWZ128((uint32_t)(mrow * 128 + kb * 2));
                ldsm_x4(ah[am], sb + off);
                ldsm_x4(al[am], sb + 16384 + off);
            }
            uint32_t bh[4][4], blf[4][4];
#pragma unroll
            for (int bb = 0; bb < 4; bb++) {
                int nrow = wn + bb * 16 + (g >> 1) * 8 + lr;
                int kb = ks * 16 + (g & 1) * 8;
                uint32_t off = SWZ128((uint32_t)(nrow * 128 + kb * 2));
                ldsm_x4(bh[bb],  sb + 32768 + off);
                ldsm_x4(blf[bb], sb + 49152 + off);
            }
#pragma unroll
            for (int am = 0; am < 2; am++)
#pragma unroll
                for (int bb = 0; bb < 4; bb++)
#pragma unroll
                    for (int h = 0; h < 2; h++) {
                        float* c = acc[am][bb * 2 + h];
                        mma16816(c, ah[am], &bh[bb][h * 2]);
                        mma16816(c, ah[am], &blf[bb][h * 2]);
                        mma16816(c, al[am], &bh[bb][h * 2]);
                    }
        }
        __syncthreads();
    }

    // ---- epilogue: +bias, store fp32 ----
    const int n_base = bn * 128 + wn;
#pragma unroll
    for (int am = 0; am < 2; am++) {
        int row = bm * 128 + wm + am * 16 + (lane >> 2);
#pragma unroll
        for (int b8 = 0; b8 < 8; b8++) {
            int n0 = n_base + b8 * 8 + (lane & 3) * 2;
            float bx = bias[n0], by = bias[n0 + 1];
            float* c = acc[am][b8];
            float2 v0 = make_float2(c[0] + bx, c[1] + by);
            float2 v1 = make_float2(c[2] + bx, c[3] + by);
            *(float2*)(g_xpre + (size_t)row * 512 + n0) = v0;
            *(float2*)(g_xpre + (size_t)(row + 8) * 512 + n0) = v1;
        }
    }
}

// ============================================================
// Kernel 2: persistent time scan, v2.
// 128 blocks x 512 threads, 2 batches per block.
// Thread j owns gate column j: weights k=0..63 in 32 packed
// f32x2 regs, k=64..127 in smem wcol[j][.] (stride 68,
// conflict-free LDS.128). Two accumulators (batch 0/1).
// ============================================================
#define WCS 68                                  // smem column stride (floats)
#define SC_WCOL  0                              // [512][68]
#define SC_HB0   (512 * WCS)                    // [128] + pad
#define SC_HB1   (SC_HB0 + 132)
#define SC_GBUF  (SC_HB1 + 132)                 // [2][512]
#define SMEM2_FLOATS (SC_GBUF + 1024 + 32)
#define SMEM2_BYTES  (SMEM2_FLOATS * 4)

__global__ __launch_bounds__(512, 1)
void lstm_scan_kernel(const float* __restrict__ c0,
                      const float* __restrict__ h0,
                      const int* __restrict__ done,   // jnp.bool_ arrives as int32
                      const float* __restrict__ Wh,   // [128][512]
                      float* __restrict__ out)
{
    extern __shared__ float smemf[];
    float* wcol = smemf + SC_WCOL;
    float* hb0  = smemf + SC_HB0;
    float* hb1  = smemf + SC_HB1;
    float* gbuf = smemf + SC_GBUF;

    const int tid = threadIdx.x;      // == gate column j, 0..511
    const int blk = blockIdx.x;
    const int b0g = blk * 2, b1g = blk * 2 + 1;

    // --- smem weights: wcol[c][k'] = Wh[64+k'][c], k'=0..63 ---
    for (int i = tid; i < 64 * 512; i += 512) {
        int kp = i >> 9, c = i & 511;          // coalesced over c
        wcol[c * WCS + kp] = Wh[(64 + kp) * 512 + c];
    }

    // --- register weights (k = 0..63), packed in k-pairs ---
    ull wreg2[32];
#pragma unroll
    for (int k = 0; k < 64; k += 2)
        wreg2[k >> 1] = fpack2(Wh[k * 512 + tid], Wh[(k + 1) * 512 + tid]);

    // --- init h buffers ---
    if (tid < 128)       hb0[tid] = h0[b0g * 128 + tid];
    else if (tid < 256)  hb1[tid - 128] = h0[b1g * 128 + (tid - 128)];

    // --- cell identity (threads 0..255 only) ---
    const int bl = (tid >> 7) & 1;
    const int jp = tid & 127;
    const int bg = blk * 2 + bl;
    float c_reg = (tid < 256) ? c0[bg * 128 + jp] : 0.0f;
    float hlast = 0.0f;

    __syncthreads();

    // --- prefetch t = 0 ---
    float x0, x1;
    int d0v, d1v;
    {
        const float* xp = g_xpre;
        x0 = xp[b0g * 512 + tid];
        x1 = xp[b1g * 512 + tid];
        d0v = done[b0g];
        d1v = done[b1g];
    }

    const float* wrow = wcol + tid * WCS;

    for (int t = 0; t < T_STEPS; t++) {
        // prefetch t+1
        float nx0 = 0.f, nx1 = 0.f;
        int nd0 = 0, nd1 = 0;
        if (t + 1 < T_STEPS) {
            const float* xp = g_xpre + (size_t)(t + 1) * (BATCH * G4);
            nx0 = xp[b0g * 512 + tid];
            nx1 = xp[b1g * 512 + tid];
            nd0 = done[(t + 1) * BATCH + b0g];
            nd1 = done[(t + 1) * BATCH + b1g];
        }

        const float k0 = d0v ? 0.0f : 1.0f;
        const float k1 = d1v ? 0.0f : 1.0f;

        // --- recurrent dot: col j, both batches, packed over k-pairs ---
        ull a0 = 0, a1 = 0;
#pragma unroll
        for (int k = 0; k < 64; k += 4) {          // k = 0..63: reg weights
            ulonglong2 h0v = *(const ulonglong2*)&hb0[k];
            ulonglong2 h1v = *(const ulonglong2*)&hb1[k];
            ull wA = wreg2[k >> 1];
            ull wB = wreg2[(k >> 1) + 1];
            a0 = ffma2(h0v.x, wA, a0);
            a1 = ffma2(h1v.x, wA, a1);
            a0 = ffma2(h0v.y, wB, a0);
            a1 = ffma2(h1v.y, wB, a1);
        }
#pragma unroll
        for (int k = 0; k < 64; k += 4) {          // k = 64..127: smem weights
            ulonglong2 h0v = *(const ulonglong2*)&hb0[64 + k];
            ulonglong2 h1v = *(const ulonglong2*)&hb1[64 + k];
            ulonglong2 wv  = *(const ulonglong2*)&wrow[k];
            a0 = ffma2(h0v.x, wv.x, a0);
            a1 = ffma2(h1v.x, wv.x, a1);
            a0 = ffma2(h0v.y, wv.y, a0);
            a1 = ffma2(h1v.y, wv.y, a1);
        }
        float rec0 = funpack_add(a0);
        float rec1 = funpack_add(a1);

        // gates = xpre + keep * rec   (h-reset applied algebraically)
        gbuf[tid]       = fmaf(k0, rec0, x0);
        gbuf[512 + tid] = fmaf(k1, rec1, x1);
        __syncthreads();

        // --- elementwise LSTM cell (threads 0..255) ---
        if (tid < 256) {
            const float* gb = gbuf + bl * 512;
            float gi = gb[jp];
            float gf = gb[128 + jp];
            float gg = gb[256 + jp];
            float go = gb[384 + jp];
            float keep = bl ? k1 : k0;
            float cprev = keep * c_reg;
            float nc = sigm_(gf) * cprev + sigm_(gi) * tanh_(gg);
            float nh = sigm_(go) * tanh_(nc);
            c_reg = nc;
            hlast = nh;
            out[(size_t)(t * BATCH + bg) * 128 + jp] = nh;
            (bl ? hb1 : hb0)[jp] = nh;
        }
        __syncthreads();

        x0 = nx0; x1 = nx1;
        d0v = nd0; d1v = nd1;
    }

    // finals: cT then hT after ys
    if (tid < 256) {
        out[(size_t)YS_ELEMS + bg * 128 + jp] = c_reg;
        out[(size_t)YS_ELEMS + BATCH * HID + bg * 128 + jp] = hlast;
    }
}

// ============================================================
extern "C" void kernel_launch(void* const* d_in, const int* in_sizes, int n_in,
                              void* d_out, int out_size)
{
    const float* c0   = (const float*)d_in[0];
    const float* h0   = (const float*)d_in[1];
    const float* obs  = (const float*)d_in[2];
    const int*   done = (const int*)d_in[3];       // jnp.bool_ -> int32
    const float* Wi   = (const float*)d_in[4];
    const float* Wh   = (const float*)d_in[5];
    const float* bias = (const float*)d_in[6];
    float* out = (float*)d_out;

    cudaFuncSetAttribute(gemm_hmma_kernel,
                         cudaFuncAttributeMaxDynamicSharedMemorySize, GSM_TOTAL);
    cudaFuncSetAttribute(lstm_scan_kernel,
                         cudaFuncAttributeMaxDynamicSharedMemorySize, SMEM2_BYTES);

    split_obs_kernel<<<1024, 256>>>(obs);
    split_wiT_kernel<<<1024, 256>>>(Wi);
    dim3 gg(4, 1024);
    gemm_hmma_kernel<<<gg, 256, GSM_TOTAL>>>(bias);
    lstm_scan_kernel<<<128, 512, SMEM2_BYTES>>>(c0, h0, done, Wh, out);
}

// round 7
// speedup vs baseline: 1.1949x; 1.1949x over previous
#include <cuda_runtime.h>
#include <cuda_bf16.h>
#include <cstdint>

// Problem constants
#define T_STEPS 512
#define BATCH   256
#define D_IN    512
#define HID     128
#define G4      512   // 4*H
#define YS_ELEMS (T_STEPS * BATCH * HID)
#define M_TOTAL  (T_STEPS * BATCH)        // 131072

typedef unsigned long long ull;

// ---------------- device scratch (static; allowed) ----------------
__device__ float          g_xpre [(size_t)M_TOTAL * G4];       // 256 MB
__device__ __nv_bfloat16  g_wiT_hi[(size_t)G4 * D_IN];         // [n][k]
__device__ __nv_bfloat16  g_wiT_lo[(size_t)G4 * D_IN];

// ---------------- small helpers ----------------
__device__ __forceinline__ ull fpack2(float lo, float hi) {
    ull r; asm("mov.b64 %0, {%1, %2};" : "=l"(r) : "f"(lo), "f"(hi)); return r;
}
__device__ __forceinline__ ull ffma2(ull a, ull b, ull c) {
    ull d; asm("fma.rn.f32x2 %0, %1, %2, %3;" : "=l"(d) : "l"(a), "l"(b), "l"(c)); return d;
}
__device__ __forceinline__ float funpack_add(ull p) {
    float lo, hi; asm("mov.b64 {%0, %1}, %2;" : "=f"(lo), "=f"(hi) : "l"(p));
    return lo + hi;
}
__device__ __forceinline__ float sigm_(float x) {
    return __fdividef(1.0f, 1.0f + __expf(-x));
}
__device__ __forceinline__ float tanh_(float x) {
    float e = __expf(-2.0f * x);
    return __fdividef(1.0f - e, 1.0f + e);
}
__device__ __forceinline__ uint32_t smem_u32(const void* p) {
    uint32_t a;
    asm("{ .reg .u64 t; cvta.to.shared.u64 t, %1; cvt.u32.u64 %0, t; }" : "=r"(a) : "l"(p));
    return a;
}

// SW128 swizzle (byte offsets within a 128B-row tile)
#define SWZ128(o) ((o) ^ (((o) >> 3) & 0x70))

__device__ __forceinline__ void cpasync16(uint32_t s, const void* g) {
    asm volatile("cp.async.cg.shared.global [%0], [%1], 16;" :: "r"(s), "l"(g));
}
__device__ __forceinline__ void ldsm_x4(uint32_t* r, uint32_t addr) {
    asm volatile("ldmatrix.sync.aligned.m8n8.x4.shared.b16 {%0,%1,%2,%3}, [%4];"
        : "=r"(r[0]), "=r"(r[1]), "=r"(r[2]), "=r"(r[3]) : "r"(addr));
}
__device__ __forceinline__ void mma16816(float* c, const uint32_t* a, const uint32_t* b) {
    asm volatile("mma.sync.aligned.m16n8k16.row.col.f32.bf16.bf16.f32 "
        "{%0,%1,%2,%3}, {%4,%5,%6,%7}, {%8,%9}, {%0,%1,%2,%3};"
        : "+f"(c[0]), "+f"(c[1]), "+f"(c[2]), "+f"(c[3])
        : "r"(a[0]), "r"(a[1]), "r"(a[2]), "r"(a[3]), "r"(b[0]), "r"(b[1]));
}
// pack 4 floats -> 4 bf16 (hi parts) as uint2-like pair of uint32
__device__ __forceinline__ void split4(const float4& v, uint32_t& hi2a, uint32_t& hi2b,
                                       uint32_t& lo2a, uint32_t& lo2b) {
    __nv_bfloat16 h0 = __float2bfloat16(v.x);
    __nv_bfloat16 h1 = __float2bfloat16(v.y);
    __nv_bfloat16 h2 = __float2bfloat16(v.z);
    __nv_bfloat16 h3 = __float2bfloat16(v.w);
    __nv_bfloat162 H01(h0, h1), H23(h2, h3);
    __nv_bfloat162 L01(__float2bfloat16(v.x - __bfloat162float(h0)),
                       __float2bfloat16(v.y - __bfloat162float(h1)));
    __nv_bfloat162 L23(__float2bfloat16(v.z - __bfloat162float(h2)),
                       __float2bfloat16(v.w - __bfloat162float(h3)));
    hi2a = *(uint32_t*)&H01; hi2b = *(uint32_t*)&H23;
    lo2a = *(uint32_t*)&L01; lo2b = *(uint32_t*)&L23;
}

// ============================================================
// Prep: transpose + split Wi [k][n] -> WiT hi/lo [n][k]
// ============================================================
__global__ __launch_bounds__(256)
void split_wiT_kernel(const float* __restrict__ Wi) {
    int idx = blockIdx.x * blockDim.x + threadIdx.x;
    if (idx < G4 * D_IN) {
        int n = idx >> 9, k = idx & 511;
        float v = Wi[k * G4 + n];
        __nv_bfloat16 h = __float2bfloat16(v);
        __nv_bfloat16 l = __float2bfloat16(v - __bfloat162float(h));
        g_wiT_hi[idx] = h;
        g_wiT_lo[idx] = l;
    }
}

// ============================================================
// GEMM via mma.sync bf16-split, obs split fused into A-path:
//   Xpre = bias + obs @ Wi  via  Ah*Bh + Ah*Bl + Al*Bh, fp32 acc
//   A: fp32 LDG (pipelined in regs) -> convert -> STS bf16 tiles
//   B: cp.async double-buffered from pre-split WiT.
// ============================================================
#define GSTAGE 65536          // Ah 16K | Al 16K | Bh 16K | Bl 16K
#define GSM_TOTAL (2 * GSTAGE)

__global__ __launch_bounds__(256, 1)
void gemm_hmma_kernel(const float* __restrict__ obs,
                      const float* __restrict__ bias)
{
    extern __shared__ __align__(1024) char smem[];
    const uint32_t smb = smem_u32(smem);
    const int tid = threadIdx.x;
    const int warp = tid >> 5, lane = tid & 31;
    const int bn = blockIdx.x;     // 0..3
    const int bm = blockIdx.y;     // 0..1023

    const float*         Aobs = obs     + (size_t)bm * 128 * 512;
    const __nv_bfloat16* Bgh  = g_wiT_hi + (size_t)bn * 128 * 512;
    const __nv_bfloat16* Bgl  = g_wiT_lo + (size_t)bn * 128 * 512;

    // B: cp.async load of Bh/Bl tiles (128 n-rows x 64 k)
    auto load_B = [&](int kc, int s) {
        uint32_t sb = smb + s * GSTAGE;
#pragma unroll
        for (int t = 0; t < 4; t++) {
            int i = tid + t * 256;
            int row = i >> 3, cc = i & 7;
            uint32_t so = SWZ128((uint32_t)(row * 128 + cc * 16));
            cpasync16(sb + 32768 + so, Bgh + (size_t)row * 512 + kc * 64 + cc * 8);
            cpasync16(sb + 49152 + so, Bgl + (size_t)row * 512 + kc * 64 + cc * 8);
        }
        asm volatile("cp.async.commit_group;" ::: "memory");
    };
    // A: fp32 LDG into regs (8 float4 per thread per stage)
    auto ldg_A = [&](int kc, float4* ar) {
#pragma unroll
        for (int t = 0; t < 4; t++) {
            int i = tid + t * 256;
            int row = i >> 3, seg = i & 7;
            const float* p = Aobs + (size_t)row * 512 + kc * 64 + seg * 8;
            ar[2 * t]     = *(const float4*)p;
            ar[2 * t + 1] = *(const float4*)(p + 4);
        }
    };
    // A: convert regs -> bf16 hi/lo, STS into swizzled tiles
    auto sts_A = [&](int s, const float4* ar) {
        uint32_t sb = smb + s * GSTAGE;
#pragma unroll
        for (int t = 0; t < 4; t++) {
            int i = tid + t * 256;
            int row = i >> 3, seg = i & 7;
            uint32_t so = SWZ128((uint32_t)(row * 128 + seg * 16));
            uint4 hi, lo;
            split4(ar[2 * t],     hi.x, hi.y, lo.x, lo.y);
            split4(ar[2 * t + 1], hi.z, hi.w, lo.z, lo.w);
            *(uint4*)(smem + s * GSTAGE + so)         = hi;
            *(uint4*)(smem + s * GSTAGE + 16384 + so) = lo;
        }
    };

    const int wm = (warp & 3) * 32;
    const int wn = (warp >> 2) * 64;
    const int lr = lane & 7, g = lane >> 3;

    float acc[2][8][4];
#pragma unroll
    for (int i = 0; i < 2; i++)
#pragma unroll
        for (int j = 0; j < 8; j++)
#pragma unroll
            for (int q = 0; q < 4; q++) acc[i][j][q] = 0.0f;

    float4 areg[8];
    ldg_A(0, areg);
    load_B(0, 0);

    for (int kc = 0; kc < 8; kc++) {
        sts_A(kc & 1, areg);
        if (kc + 1 < 8) {
            ldg_A(kc + 1, areg);          // prefetch next stage into regs
            load_B(kc + 1, (kc + 1) & 1);
            asm volatile("cp.async.wait_group 1;" ::: "memory");
        } else {
            asm volatile("cp.async.wait_group 0;" ::: "memory");
        }
        __syncthreads();                  // STS drain + B visible

        uint32_t sb = smb + (kc & 1) * GSTAGE;
#pragma unroll
        for (int ks = 0; ks < 4; ks++) {
            uint32_t ah[2][4], al[2][4];
#pragma unroll
            for (int am = 0; am < 2; am++) {
                int mrow = wm + am * 16 + (g & 1) * 8 + lr;
                int kb = ks * 16 + (g >> 1) * 8;
                uint32_t off = SWZ128((uint32_t)(mrow * 128 + kb * 2));
                ldsm_x4(ah[am], sb + off);
                ldsm_x4(al[am], sb + 16384 + off);
            }
            uint32_t bh[4][4], blf[4][4];
#pragma unroll
            for (int bb = 0; bb < 4; bb++) {
                int nrow = wn + bb * 16 + (g >> 1) * 8 + lr;
                int kb = ks * 16 + (g & 1) * 8;
                uint32_t off = SWZ128((uint32_t)(nrow * 128 + kb * 2));
                ldsm_x4(bh[bb],  sb + 32768 + off);
                ldsm_x4(blf[bb], sb + 49152 + off);
            }
#pragma unroll
            for (int am = 0; am < 2; am++)
#pragma unroll
                for (int bb = 0; bb < 4; bb++)
#pragma unroll
                    for (int h = 0; h < 2; h++) {
                        float* c = acc[am][bb * 2 + h];
                        mma16816(c, ah[am], &bh[bb][h * 2]);
                        mma16816(c, ah[am], &blf[bb][h * 2]);
                        mma16816(c, al[am], &bh[bb][h * 2]);
                    }
        }
        __syncthreads();
    }

    // ---- epilogue: +bias, store fp32 ----
    const int n_base = bn * 128 + wn;
#pragma unroll
    for (int am = 0; am < 2; am++) {
        int row = bm * 128 + wm + am * 16 + (lane >> 2);
#pragma unroll
        for (int b8 = 0; b8 < 8; b8++) {
            int n0 = n_base + b8 * 8 + (lane & 3) * 2;
            float bx = bias[n0], by = bias[n0 + 1];
            float* c = acc[am][b8];
            float2 v0 = make_float2(c[0] + bx, c[1] + by);
            float2 v1 = make_float2(c[2] + bx, c[3] + by);
            *(float2*)(g_xpre + (size_t)row * 512 + n0) = v0;
            *(float2*)(g_xpre + (size_t)(row + 8) * 512 + n0) = v1;
        }
    }
}

// ============================================================
// Kernel 2: persistent time scan v4 (R3 shape, more reg weights).
// 128 blocks x 256 threads, 2 batches/block. Thread t owns cols
// j0=t (128 w in regs) and j1=256+t (k<32 in regs, k=32..127 in
// smem, stride 100 -> conflict-free LDS.128).
// ============================================================
#define WHS_STRIDE 100
#define SMEM2_FLOATS (256 * WHS_STRIDE + 132 + 132 + 1024 + 32)
#define SMEM2_BYTES  (SMEM2_FLOATS * 4)

__global__ __launch_bounds__(256, 1)
void lstm_scan_kernel(const float* __restrict__ c0,
                      const float* __restrict__ h0,
                      const int* __restrict__ done,   // jnp.bool_ arrives as int32
                      const float* __restrict__ Wh,   // [128][512]
                      float* __restrict__ out)
{
    extern __shared__ float smemf[];
    float* whs  = smemf;                          // [256 cols][100] k=32..127
    float* hb0  = smemf + 256 * WHS_STRIDE;
    float* hb1  = hb0 + 132;
    float* gbuf = hb1 + 132;

    const int tid = threadIdx.x;
    const int blk = blockIdx.x;
    const int b0g = blk * 2, b1g = blk * 2 + 1;

    // --- smem weights: whs[c][kp] = Wh[32+kp][256+c], kp=0..95 ---
    for (int i = tid; i < 96 * 256; i += 256) {
        int kp = i >> 8, c = i & 255;                 // coalesced over c
        whs[c * WHS_STRIDE + kp] = Wh[(32 + kp) * 512 + 256 + c];
    }

    // --- register weights ---
    // [0..63]  : col j0=tid,     k-pairs 0..63
    // [64..79] : col j1=256+tid, k-pairs 0..15 (k=0..31)
    ull wreg2[80];
#pragma unroll
    for (int k = 0; k < 128; k += 2)
        wreg2[k >> 1] = fpack2(Wh[k * 512 + tid], Wh[(k + 1) * 512 + tid]);
#pragma unroll
    for (int k = 0; k < 32; k += 2)
        wreg2[64 + (k >> 1)] = fpack2(Wh[k * 512 + 256 + tid], Wh[(k + 1) * 512 + 256 + tid]);

    // --- init h buffers ---
    if (tid < 128) hb0[tid] = h0[b0g * 128 + tid];
    else           hb1[tid - 128] = h0[b1g * 128 + (tid - 128)];

    const int bl = tid >> 7;
    const int jp = tid & 127;
    const int bg = blk * 2 + bl;
    float c_reg = c0[bg * 128 + jp];
    float hlast = 0.0f;

    __syncthreads();

    // --- prefetch t = 0 ---
    float x00, x01, x10, x11;
    int d0v, d1v;
    {
        const float* xp = g_xpre;
        x00 = xp[b0g * 512 + tid];
        x01 = xp[b0g * 512 + 256 + tid];
        x10 = xp[b1g * 512 + tid];
        x11 = xp[b1g * 512 + 256 + tid];
        d0v = done[b0g];
        d1v = done[b1g];
    }

    const float* wrow = whs + tid * WHS_STRIDE;
    float* myh = bl ? hb1 : hb0;

    for (int t = 0; t < T_STEPS; t++) {
        // prefetch t+1
        float nx00 = 0.f, nx01 = 0.f, nx10 = 0.f, nx11 = 0.f;
        int nd0 = 0, nd1 = 0;
        if (t + 1 < T_STEPS) {
            const float* xp = g_xpre + (size_t)(t + 1) * (BATCH * G4);
            nx00 = xp[b0g * 512 + tid];
            nx01 = xp[b0g * 512 + 256 + tid];
            nx10 = xp[b1g * 512 + tid];
            nx11 = xp[b1g * 512 + 256 + tid];
            nd0 = done[(t + 1) * BATCH + b0g];
            nd1 = done[(t + 1) * BATCH + b1g];
        }

        const float k0 = d0v ? 0.0f : 1.0f;
        const float k1 = d1v ? 0.0f : 1.0f;

        ull a00 = 0, a01 = 0, a10 = 0, a11 = 0;
        // k = 0..31: both columns' weights in regs
#pragma unroll
        for (int k = 0; k < 32; k += 4) {
            ulonglong2 h0v = *(const ulonglong2*)&hb0[k];
            ulonglong2 h1v = *(const ulonglong2*)&hb1[k];
            ull wA  = wreg2[k >> 1];
            ull wB  = wreg2[(k >> 1) + 1];
            ull w1A = wreg2[64 + (k >> 1)];
            ull w1B = wreg2[64 + (k >> 1) + 1];
            a00 = ffma2(h0v.x, wA,  a00);
            a10 = ffma2(h1v.x, wA,  a10);
            a01 = ffma2(h0v.x, w1A, a01);
            a11 = ffma2(h1v.x, w1A, a11);
            a00 = ffma2(h0v.y, wB,  a00);
            a10 = ffma2(h1v.y, wB,  a10);
            a01 = ffma2(h0v.y, w1B, a01);
            a11 = ffma2(h1v.y, w1B, a11);
        }
        // k = 32..127: j0 weights in regs, j1 weights from smem
#pragma unroll
        for (int k = 32; k < 128; k += 4) {
            ulonglong2 h0v = *(const ulonglong2*)&hb0[k];
            ulonglong2 h1v = *(const ulonglong2*)&hb1[k];
            ulonglong2 w1v = *(const ulonglong2*)&wrow[k - 32];
            ull wA = wreg2[k >> 1];
            ull wB = wreg2[(k >> 1) + 1];
            a00 = ffma2(h0v.x, wA,    a00);
            a10 = ffma2(h1v.x, wA,    a10);
            a01 = ffma2(h0v.x, w1v.x, a01);
            a11 = ffma2(h1v.x, w1v.x, a11);
            a00 = ffma2(h0v.y, wB,    a00);
            a10 = ffma2(h1v.y, wB,    a10);
            a01 = ffma2(h0v.y, w1v.y, a01);
            a11 = ffma2(h1v.y, w1v.y, a11);
        }
        float rec00 = funpack_add(a00);
        float rec10 = funpack_add(a10);
        float rec01 = funpack_add(a01);
        float rec11 = funpack_add(a11);

        // gates = xpre + keep * rec
        gbuf[tid]             = fmaf(k0, rec00, x00);
        gbuf[512 + tid]       = fmaf(k1, rec10, x10);
        gbuf[256 + tid]       = fmaf(k0, rec01, x01);
        gbuf[512 + 256 + tid] = fmaf(k1, rec11, x11);
        __syncthreads();

        // --- elementwise LSTM cell ---
        {
            const float* gb = gbuf + bl * 512;
            float gi = gb[jp];
            float gf = gb[128 + jp];
            float gg = gb[256 + jp];
            float go = gb[384 + jp];
            float keep = bl ? k1 : k0;
            float cprev = keep * c_reg;
            float nc = sigm_(gf) * cprev + sigm_(gi) * tanh_(gg);
            float nh = sigm_(go) * tanh_(nc);
            c_reg = nc;
            hlast = nh;
            out[(size_t)(t * BATCH + bg) * 128 + jp] = nh;
            myh[jp] = nh;
        }
        __syncthreads();

        x00 = nx00; x01 = nx01; x10 = nx10; x11 = nx11;
        d0v = nd0;  d1v = nd1;
    }

    out[(size_t)YS_ELEMS + bg * 128 + jp] = c_reg;
    out[(size_t)YS_ELEMS + BATCH * HID + bg * 128 + jp] = hlast;
}

// ============================================================
extern "C" void kernel_launch(void* const* d_in, const int* in_sizes, int n_in,
                              void* d_out, int out_size)
{
    const float* c0   = (const float*)d_in[0];
    const float* h0   = (const float*)d_in[1];
    const float* obs  = (const float*)d_in[2];
    const int*   done = (const int*)d_in[3];       // jnp.bool_ -> int32
    const float* Wi   = (const float*)d_in[4];
    const float* Wh   = (const float*)d_in[5];
    const float* bias = (const float*)d_in[6];
    float* out = (float*)d_out;

    cudaFuncSetAttribute(gemm_hmma_kernel,
                         cudaFuncAttributeMaxDynamicSharedMemorySize, GSM_TOTAL);
    cudaFuncSetAttribute(lstm_scan_kernel,
                         cudaFuncAttributeMaxDynamicSharedMemorySize, SMEM2_BYTES);

    split_wiT_kernel<<<1024, 256>>>(Wi);
    dim3 gg(4, 1024);
    gemm_hmma_kernel<<<gg, 256, GSM_TOTAL>>>(obs, bias);
    lstm_scan_kernel<<<128, 256, SMEM2_BYTES>>>(c0, h0, done, Wh, out);
}

// round 8
// speedup vs baseline: 1.2336x; 1.0323x over previous
#include <cuda_runtime.h>
#include <cuda_bf16.h>
#include <cstdint>

// Problem constants
#define T_STEPS 512
#define BATCH   256
#define D_IN    512
#define HID     128
#define G4      512   // 4*H
#define YS_ELEMS (T_STEPS * BATCH * HID)
#define M_TOTAL  (T_STEPS * BATCH)        // 131072

typedef unsigned long long ull;

// ---------------- device scratch (static; allowed) ----------------
__device__ float          g_xpre [(size_t)M_TOTAL * G4];       // 256 MB
__device__ __nv_bfloat16  g_wiT_hi[(size_t)G4 * D_IN];         // [n][k]
__device__ __nv_bfloat16  g_wiT_lo[(size_t)G4 * D_IN];

// ---------------- small helpers ----------------
__device__ __forceinline__ ull fpack2(float lo, float hi) {
    ull r; asm("mov.b64 %0, {%1, %2};" : "=l"(r) : "f"(lo), "f"(hi)); return r;
}
__device__ __forceinline__ ull ffma2(ull a, ull b, ull c) {
    ull d; asm("fma.rn.f32x2 %0, %1, %2, %3;" : "=l"(d) : "l"(a), "l"(b), "l"(c)); return d;
}
__device__ __forceinline__ float funpack_add(ull p) {
    float lo, hi; asm("mov.b64 {%0, %1}, %2;" : "=f"(lo), "=f"(hi) : "l"(p));
    return lo + hi;
}
__device__ __forceinline__ float sigm_(float x) {
    return __fdividef(1.0f, 1.0f + __expf(-x));
}
__device__ __forceinline__ float tanh_(float x) {
    float e = __expf(-2.0f * x);
    return __fdividef(1.0f - e, 1.0f + e);
}
__device__ __forceinline__ uint32_t smem_u32(const void* p) {
    uint32_t a;
    asm("{ .reg .u64 t; cvta.to.shared.u64 t, %1; cvt.u32.u64 %0, t; }" : "=r"(a) : "l"(p));
    return a;
}

// SW128 swizzle (byte offsets within a 128B-row tile)
#define SWZ128(o) ((o) ^ (((o) >> 3) & 0x70))

__device__ __forceinline__ void cpasync16(uint32_t s, const void* g) {
    asm volatile("cp.async.cg.shared.global [%0], [%1], 16;" :: "r"(s), "l"(g));
}
__device__ __forceinline__ void ldsm_x4(uint32_t* r, uint32_t addr) {
    asm volatile("ldmatrix.sync.aligned.m8n8.x4.shared.b16 {%0,%1,%2,%3}, [%4];"
        : "=r"(r[0]), "=r"(r[1]), "=r"(r[2]), "=r"(r[3]) : "r"(addr));
}
__device__ __forceinline__ void mma16816(float* c, const uint32_t* a, const uint32_t* b) {
    asm volatile("mma.sync.aligned.m16n8k16.row.col.f32.bf16.bf16.f32 "
        "{%0,%1,%2,%3}, {%4,%5,%6,%7}, {%8,%9}, {%0,%1,%2,%3};"
        : "+f"(c[0]), "+f"(c[1]), "+f"(c[2]), "+f"(c[3])
        : "r"(a[0]), "r"(a[1]), "r"(a[2]), "r"(a[3]), "r"(b[0]), "r"(b[1]));
}
// pack 4 floats -> bf16 hi/lo pairs
__device__ __forceinline__ void split4(const float4& v, uint32_t& hi2a, uint32_t& hi2b,
                                       uint32_t& lo2a, uint32_t& lo2b) {
    __nv_bfloat16 h0 = __float2bfloat16(v.x);
    __nv_bfloat16 h1 = __float2bfloat16(v.y);
    __nv_bfloat16 h2 = __float2bfloat16(v.z);
    __nv_bfloat16 h3 = __float2bfloat16(v.w);
    __nv_bfloat162 H01(h0, h1), H23(h2, h3);
    __nv_bfloat162 L01(__float2bfloat16(v.x - __bfloat162float(h0)),
                       __float2bfloat16(v.y - __bfloat162float(h1)));
    __nv_bfloat162 L23(__float2bfloat16(v.z - __bfloat162float(h2)),
                       __float2bfloat16(v.w - __bfloat162float(h3)));
    hi2a = *(uint32_t*)&H01; hi2b = *(uint32_t*)&H23;
    lo2a = *(uint32_t*)&L01; lo2b = *(uint32_t*)&L23;
}

// ============================================================
// Prep: transpose + split Wi [k][n] -> WiT hi/lo [n][k]
// ============================================================
__global__ __launch_bounds__(256)
void split_wiT_kernel(const float* __restrict__ Wi) {
    int idx = blockIdx.x * blockDim.x + threadIdx.x;
    if (idx < G4 * D_IN) {
        int n = idx >> 9, k = idx & 511;
        float v = Wi[k * G4 + n];
        __nv_bfloat16 h = __float2bfloat16(v);
        __nv_bfloat16 l = __float2bfloat16(v - __bfloat162float(h));
        g_wiT_hi[idx] = h;
        g_wiT_lo[idx] = l;
    }
}

// ============================================================
// GEMM via mma.sync bf16-split, obs split fused into A-path
// (verified in R7, unchanged)
// ============================================================
#define GSTAGE 65536          // Ah 16K | Al 16K | Bh 16K | Bl 16K
#define GSM_TOTAL (2 * GSTAGE)

__global__ __launch_bounds__(256, 1)
void gemm_hmma_kernel(const float* __restrict__ obs,
                      const float* __restrict__ bias)
{
    extern __shared__ __align__(1024) char smem[];
    const uint32_t smb = smem_u32(smem);
    const int tid = threadIdx.x;
    const int warp = tid >> 5, lane = tid & 31;
    const int bn = blockIdx.x;     // 0..3
    const int bm = blockIdx.y;     // 0..1023

    const float*         Aobs = obs      + (size_t)bm * 128 * 512;
    const __nv_bfloat16* Bgh  = g_wiT_hi + (size_t)bn * 128 * 512;
    const __nv_bfloat16* Bgl  = g_wiT_lo + (size_t)bn * 128 * 512;

    auto load_B = [&](int kc, int s) {
        uint32_t sb = smb + s * GSTAGE;
#pragma unroll
        for (int t = 0; t < 4; t++) {
            int i = tid + t * 256;
            int row = i >> 3, cc = i & 7;
            uint32_t so = SWZ128((uint32_t)(row * 128 + cc * 16));
            cpasync16(sb + 32768 + so, Bgh + (size_t)row * 512 + kc * 64 + cc * 8);
            cpasync16(sb + 49152 + so, Bgl + (size_t)row * 512 + kc * 64 + cc * 8);
        }
        asm volatile("cp.async.commit_group;" ::: "memory");
    };
    auto ldg_A = [&](int kc, float4* ar) {
#pragma unroll
        for (int t = 0; t < 4; t++) {
            int i = tid + t * 256;
            int row = i >> 3, seg = i & 7;
            const float* p = Aobs + (size_t)row * 512 + kc * 64 + seg * 8;
            ar[2 * t]     = *(const float4*)p;
            ar[2 * t + 1] = *(const float4*)(p + 4);
        }
    };
    auto sts_A = [&](int s, const float4* ar) {
#pragma unroll
        for (int t = 0; t < 4; t++) {
            int i = tid + t * 256;
            int row = i >> 3, seg = i & 7;
            uint32_t so = SWZ128((uint32_t)(row * 128 + seg * 16));
            uint4 hi, lo;
            split4(ar[2 * t],     hi.x, hi.y, lo.x, lo.y);
            split4(ar[2 * t + 1], hi.z, hi.w, lo.z, lo.w);
            *(uint4*)(smem + s * GSTAGE + so)         = hi;
            *(uint4*)(smem + s * GSTAGE + 16384 + so) = lo;
        }
    };

    const int wm = (warp & 3) * 32;
    const int wn = (warp >> 2) * 64;
    const int lr = lane & 7, g = lane >> 3;

    float acc[2][8][4];
#pragma unroll
    for (int i = 0; i < 2; i++)
#pragma unroll
        for (int j = 0; j < 8; j++)
#pragma unroll
            for (int q = 0; q < 4; q++) acc[i][j][q] = 0.0f;

    float4 areg[8];
    ldg_A(0, areg);
    load_B(0, 0);

    for (int kc = 0; kc < 8; kc++) {
        sts_A(kc & 1, areg);
        if (kc + 1 < 8) {
            ldg_A(kc + 1, areg);
            load_B(kc + 1, (kc + 1) & 1);
            asm volatile("cp.async.wait_group 1;" ::: "memory");
        } else {
            asm volatile("cp.async.wait_group 0;" ::: "memory");
        }
        __syncthreads();

        uint32_t sb = smb + (kc & 1) * GSTAGE;
#pragma unroll
        for (int ks = 0; ks < 4; ks++) {
            uint32_t ah[2][4], al[2][4];
#pragma unroll
            for (int am = 0; am < 2; am++) {
                int mrow = wm + am * 16 + (g & 1) * 8 + lr;
                int kb = ks * 16 + (g >> 1) * 8;
                uint32_t off = SWZ128((uint32_t)(mrow * 128 + kb * 2));
                ldsm_x4(ah[am], sb + off);
                ldsm_x4(al[am], sb + 16384 + off);
            }
            uint32_t bh[4][4], blf[4][4];
#pragma unroll
            for (int bb = 0; bb < 4; bb++) {
                int nrow = wn + bb * 16 + (g >> 1) * 8 + lr;
                int kb = ks * 16 + (g & 1) * 8;
                uint32_t off = SWZ128((uint32_t)(nrow * 128 + kb * 2));
                ldsm_x4(bh[bb],  sb + 32768 + off);
                ldsm_x4(blf[bb], sb + 49152 + off);
            }
#pragma unroll
            for (int am = 0; am < 2; am++)
#pragma unroll
                for (int bb = 0; bb < 4; bb++)
#pragma unroll
                    for (int h = 0; h < 2; h++) {
                        float* c = acc[am][bb * 2 + h];
                        mma16816(c, ah[am], &bh[bb][h * 2]);
                        mma16816(c, ah[am], &blf[bb][h * 2]);
                        mma16816(c, al[am], &bh[bb][h * 2]);
                    }
        }
        __syncthreads();
    }

    const int n_base = bn * 128 + wn;
#pragma unroll
    for (int am = 0; am < 2; am++) {
        int row = bm * 128 + wm + am * 16 + (lane >> 2);
#pragma unroll
        for (int b8 = 0; b8 < 8; b8++) {
            int n0 = n_base + b8 * 8 + (lane & 3) * 2;
            float bx = bias[n0], by = bias[n0 + 1];
            float* c = acc[am][b8];
            float2 v0 = make_float2(c[0] + bx, c[1] + by);
            float2 v1 = make_float2(c[2] + bx, c[3] + by);
            *(float2*)(g_xpre + (size_t)row * 512 + n0) = v0;
            *(float2*)(g_xpre + (size_t)(row + 8) * 512 + n0) = v1;
        }
    }
}

// ============================================================
// Kernel 2: persistent time scan v5.
// 128 blocks x 256 threads, 2 batches/block.
// Threads 0..127 -> batch0, 128..255 -> batch1 (warp-coherent).
// Thread owns hidden unit j = tid&127, computes ALL 4 gate cols
// (j, j+128, j+256, j+384) -> LSTM cell fused in registers,
// no gbuf, 1 barrier/step, done-steps skip the whole rec loop.
// Weights: k=0..39 in 80 ull regs, k=40..127 in smem [512][92].
// h double-buffered by step parity.
// ============================================================
#define WSS 92                                   // smem weight stride (floats)
#define SC_W    0                                // [512 cols][92]
#define SC_H    (512 * WSS)                      // 2 parities x 2 batches x 132
#define SMEM2_FLOATS (SC_H + 2 * 2 * 132 + 32)
#define SMEM2_BYTES  (SMEM2_FLOATS * 4)

__global__ __launch_bounds__(256, 1)
void lstm_scan_kernel(const float* __restrict__ c0,
                      const float* __restrict__ h0,
                      const int* __restrict__ done,   // jnp.bool_ arrives as int32
                      const float* __restrict__ Wh,   // [128][512]
                      float* __restrict__ out)
{
    extern __shared__ float smemf[];
    float* wsm = smemf + SC_W;       // wsm[col*WSS + (k-40)], k=40..127
    float* hbb = smemf + SC_H;       // [par][bl][132]

    const int tid = threadIdx.x;
    const int blk = blockIdx.x;
    const int bl  = tid >> 7;                    // batch lane 0/1
    const int jp  = tid & 127;                   // hidden unit
    const int bg  = blk * 2 + bl;                // global batch

    // --- fill smem weights: wsm[col][kp] = Wh[40+kp][col], kp=0..87 ---
    for (int i = tid; i < 88 * 512; i += 256) {
        int kp = i >> 9, col = i & 511;          // coalesced over col
        wsm[col * WSS + kp] = Wh[(40 + kp) * 512 + col];
    }

    // --- register weights: 4 cols x k=0..39 packed ---
    ull wreg2[4][20];
#pragma unroll
    for (int c = 0; c < 4; c++) {
        const int col = jp + 128 * c;
#pragma unroll
        for (int k = 0; k < 40; k += 2)
            wreg2[c][k >> 1] = fpack2(Wh[k * 512 + col], Wh[(k + 1) * 512 + col]);
    }

    // --- init h parity buffer 0 ---
    if (tid < 128)      hbb[0 * 264 + 0 * 132 + tid] = h0[(blk * 2 + 0) * 128 + tid];
    else                hbb[0 * 264 + 1 * 132 + (tid - 128)] = h0[(blk * 2 + 1) * 128 + (tid - 128)];

    float c_reg = c0[bg * 128 + jp];
    float hlast = 0.0f;

    __syncthreads();

    // --- prefetch t = 0 ---
    float x0, x1, x2, x3;
    int dv;
    {
        const float* xp = g_xpre + (size_t)bg * 512;
        x0 = xp[jp]; x1 = xp[128 + jp]; x2 = xp[256 + jp]; x3 = xp[384 + jp];
        dv = done[bg];
    }

    for (int t = 0; t < T_STEPS; t++) {
        // prefetch t+1
        float nx0 = 0.f, nx1 = 0.f, nx2 = 0.f, nx3 = 0.f;
        int ndv = 0;
        if (t + 1 < T_STEPS) {
            const float* xp = g_xpre + ((size_t)(t + 1) * BATCH + bg) * 512;
            nx0 = xp[jp]; nx1 = xp[128 + jp]; nx2 = xp[256 + jp]; nx3 = xp[384 + jp];
            ndv = done[(t + 1) * BATCH + bg];
        }

        const float* hb = hbb + (t & 1) * 264 + bl * 132;   // read buffer
        float gi = x0, gf = x1, gg = x2, go = x3;
        float keep;

        if (dv == 0) {
            keep = 1.0f;
            ull a0 = 0, a1 = 0, a2 = 0, a3 = 0;
#pragma unroll
            for (int k = 0; k < 40; k += 4) {
                ulonglong2 hv = *(const ulonglong2*)&hb[k];
                a0 = ffma2(hv.x, wreg2[0][k >> 1], a0);
                a1 = ffma2(hv.x, wreg2[1][k >> 1], a1);
                a2 = ffma2(hv.x, wreg2[2][k >> 1], a2);
                a3 = ffma2(hv.x, wreg2[3][k >> 1], a3);
                a0 = ffma2(hv.y, wreg2[0][(k >> 1) + 1], a0);
                a1 = ffma2(hv.y, wreg2[1][(k >> 1) + 1], a1);
                a2 = ffma2(hv.y, wreg2[2][(k >> 1) + 1], a2);
                a3 = ffma2(hv.y, wreg2[3][(k >> 1) + 1], a3);
            }
#pragma unroll
            for (int k = 40; k < 128; k += 4) {
                ulonglong2 hv = *(const ulonglong2*)&hb[k];
                ulonglong2 w0 = *(const ulonglong2*)&wsm[(jp          ) * WSS + (k - 40)];
                ulonglong2 w1 = *(const ulonglong2*)&wsm[(jp + 128    ) * WSS + (k - 40)];
                ulonglong2 w2 = *(const ulonglong2*)&wsm[(jp + 256    ) * WSS + (k - 40)];
                ulonglong2 w3 = *(const ulonglong2*)&wsm[(jp + 384    ) * WSS + (k - 40)];
                a0 = ffma2(hv.x, w0.x, a0);
                a1 = ffma2(hv.x, w1.x, a1);
                a2 = ffma2(hv.x, w2.x, a2);
                a3 = ffma2(hv.x, w3.x, a3);
                a0 = ffma2(hv.y, w0.y, a0);
                a1 = ffma2(hv.y, w1.y, a1);
                a2 = ffma2(hv.y, w2.y, a2);
                a3 = ffma2(hv.y, w3.y, a3);
            }
            gi += funpack_add(a0);
            gf += funpack_add(a1);
            gg += funpack_add(a2);
            go += funpack_add(a3);
        } else {
            keep = 0.0f;
        }

        // --- fused LSTM cell ---
        float cprev = keep * c_reg;
        float nc = sigm_(gf) * cprev + sigm_(gi) * tanh_(gg);
        float nh = sigm_(go) * tanh_(nc);
        c_reg = nc;
        hlast = nh;
        out[(size_t)(t * BATCH + bg) * 128 + jp] = nh;
        hbb[((t + 1) & 1) * 264 + bl * 132 + jp] = nh;   // write other parity

        __syncthreads();

        x0 = nx0; x1 = nx1; x2 = nx2; x3 = nx3;
        dv = ndv;
    }

    // finals: cT then hT after ys
    out[(size_t)YS_ELEMS + bg * 128 + jp] = c_reg;
    out[(size_t)YS_ELEMS + BATCH * HID + bg * 128 + jp] = hlast;
}

// ============================================================
extern "C" void kernel_launch(void* const* d_in, const int* in_sizes, int n_in,
                              void* d_out, int out_size)
{
    const float* c0   = (const float*)d_in[0];
    const float* h0   = (const float*)d_in[1];
    const float* obs  = (const float*)d_in[2];
    const int*   done = (const int*)d_in[3];       // jnp.bool_ -> int32
    const float* Wi   = (const float*)d_in[4];
    const float* Wh   = (const float*)d_in[5];
    const float* bias = (const float*)d_in[6];
    float* out = (float*)d_out;

    cudaFuncSetAttribute(gemm_hmma_kernel,
                         cudaFuncAttributeMaxDynamicSharedMemorySize, GSM_TOTAL);
    cudaFuncSetAttribute(lstm_scan_kernel,
                         cudaFuncAttributeMaxDynamicSharedMemorySize, SMEM2_BYTES);

    split_wiT_kernel<<<1024, 256>>>(Wi);
    dim3 gg(4, 1024);
    gemm_hmma_kernel<<<gg, 256, GSM_TOTAL>>>(obs, bias);
    lstm_scan_kernel<<<128, 256, SMEM2_BYTES>>>(c0, h0, done, Wh, out);
}

// round 9
// speedup vs baseline: 1.2688x; 1.0285x over previous
#include <cuda_runtime.h>
#include <cuda_bf16.h>
#include <cstdint>

// Problem constants
#define T_STEPS 512
#define BATCH   256
#define D_IN    512
#define HID     128
#define G4      512   // 4*H
#define YS_ELEMS (T_STEPS * BATCH * HID)
#define M_TOTAL  (T_STEPS * BATCH)        // 131072

typedef unsigned long long ull;

// ---------------- device scratch (static; allowed) ----------------
__device__ float          g_xpre [(size_t)M_TOTAL * G4];       // 256 MB
__device__ __nv_bfloat16  g_wiT_hi[(size_t)G4 * D_IN];         // [n][k]
__device__ __nv_bfloat16  g_wiT_lo[(size_t)G4 * D_IN];

// ---------------- small helpers ----------------
__device__ __forceinline__ ull fpack2(float lo, float hi) {
    ull r; asm("mov.b64 %0, {%1, %2};" : "=l"(r) : "f"(lo), "f"(hi)); return r;
}
__device__ __forceinline__ ull ffma2(ull a, ull b, ull c) {
    ull d; asm("fma.rn.f32x2 %0, %1, %2, %3;" : "=l"(d) : "l"(a), "l"(b), "l"(c)); return d;
}
__device__ __forceinline__ float funpack_add(ull p) {
    float lo, hi; asm("mov.b64 {%0, %1}, %2;" : "=f"(lo), "=f"(hi) : "l"(p));
    return lo + hi;
}
__device__ __forceinline__ float sigm_(float x) {
    return __fdividef(1.0f, 1.0f + __expf(-x));
}
__device__ __forceinline__ float tanh_(float x) {
    float e = __expf(-2.0f * x);
    return __fdividef(1.0f - e, 1.0f + e);
}
__device__ __forceinline__ uint32_t smem_u32(const void* p) {
    uint32_t a;
    asm("{ .reg .u64 t; cvta.to.shared.u64 t, %1; cvt.u32.u64 %0, t; }" : "=r"(a) : "l"(p));
    return a;
}

// SW128 swizzle (byte offsets within a 128B-row tile)
#define SWZ128(o) ((o) ^ (((o) >> 3) & 0x70))

__device__ __forceinline__ void cpasync16(uint32_t s, const void* g) {
    asm volatile("cp.async.cg.shared.global [%0], [%1], 16;" :: "r"(s), "l"(g));
}
__device__ __forceinline__ void ldsm_x4(uint32_t* r, uint32_t addr) {
    asm volatile("ldmatrix.sync.aligned.m8n8.x4.shared.b16 {%0,%1,%2,%3}, [%4];"
        : "=r"(r[0]), "=r"(r[1]), "=r"(r[2]), "=r"(r[3]) : "r"(addr));
}
__device__ __forceinline__ void mma16816(float* c, const uint32_t* a, const uint32_t* b) {
    asm volatile("mma.sync.aligned.m16n8k16.row.col.f32.bf16.bf16.f32 "
        "{%0,%1,%2,%3}, {%4,%5,%6,%7}, {%8,%9}, {%0,%1,%2,%3};"
        : "+f"(c[0]), "+f"(c[1]), "+f"(c[2]), "+f"(c[3])
        : "r"(a[0]), "r"(a[1]), "r"(a[2]), "r"(a[3]), "r"(b[0]), "r"(b[1]));
}
// pack 4 floats -> bf16 hi/lo pairs
__device__ __forceinline__ void split4(const float4& v, uint32_t& hi2a, uint32_t& hi2b,
                                       uint32_t& lo2a, uint32_t& lo2b) {
    __nv_bfloat16 h0 = __float2bfloat16(v.x);
    __nv_bfloat16 h1 = __float2bfloat16(v.y);
    __nv_bfloat16 h2 = __float2bfloat16(v.z);
    __nv_bfloat16 h3 = __float2bfloat16(v.w);
    __nv_bfloat162 H01(h0, h1), H23(h2, h3);
    __nv_bfloat162 L01(__float2bfloat16(v.x - __bfloat162float(h0)),
                       __float2bfloat16(v.y - __bfloat162float(h1)));
    __nv_bfloat162 L23(__float2bfloat16(v.z - __bfloat162float(h2)),
                       __float2bfloat16(v.w - __bfloat162float(h3)));
    hi2a = *(uint32_t*)&H01; hi2b = *(uint32_t*)&H23;
    lo2a = *(uint32_t*)&L01; lo2b = *(uint32_t*)&L23;
}

// ============================================================
// Prep: transpose + split Wi [k][n] -> WiT hi/lo [n][k]
// ============================================================
__global__ __launch_bounds__(256)
void split_wiT_kernel(const float* __restrict__ Wi) {
    int idx = blockIdx.x * blockDim.x + threadIdx.x;
    if (idx < G4 * D_IN) {
        int n = idx >> 9, k = idx & 511;
        float v = Wi[k * G4 + n];
        __nv_bfloat16 h = __float2bfloat16(v);
        __nv_bfloat16 l = __float2bfloat16(v - __bfloat162float(h));
        g_wiT_hi[idx] = h;
        g_wiT_lo[idx] = l;
    }
}

// ============================================================
// GEMM via mma.sync bf16-split, obs split fused into A-path
// (verified in R7/R8, unchanged)
// ============================================================
#define GSTAGE 65536          // Ah 16K | Al 16K | Bh 16K | Bl 16K
#define GSM_TOTAL (2 * GSTAGE)

__global__ __launch_bounds__(256, 1)
void gemm_hmma_kernel(const float* __restrict__ obs,
                      const float* __restrict__ bias)
{
    extern __shared__ __align__(1024) char smem[];
    const uint32_t smb = smem_u32(smem);
    const int tid = threadIdx.x;
    const int warp = tid >> 5, lane = tid & 31;
    const int bn = blockIdx.x;     // 0..3
    const int bm = blockIdx.y;     // 0..1023

    const float*         Aobs = obs      + (size_t)bm * 128 * 512;
    const __nv_bfloat16* Bgh  = g_wiT_hi + (size_t)bn * 128 * 512;
    const __nv_bfloat16* Bgl  = g_wiT_lo + (size_t)bn * 128 * 512;

    auto load_B = [&](int kc, int s) {
        uint32_t sb = smb + s * GSTAGE;
#pragma unroll
        for (int t = 0; t < 4; t++) {
            int i = tid + t * 256;
            int row = i >> 3, cc = i & 7;
            uint32_t so = SWZ128((uint32_t)(row * 128 + cc * 16));
            cpasync16(sb + 32768 + so, Bgh + (size_t)row * 512 + kc * 64 + cc * 8);
            cpasync16(sb + 49152 + so, Bgl + (size_t)row * 512 + kc * 64 + cc * 8);
        }
        asm volatile("cp.async.commit_group;" ::: "memory");
    };
    auto ldg_A = [&](int kc, float4* ar) {
#pragma unroll
        for (int t = 0; t < 4; t++) {
            int i = tid + t * 256;
            int row = i >> 3, seg = i & 7;
            const float* p = Aobs + (size_t)row * 512 + kc * 64 + seg * 8;
            ar[2 * t]     = *(const float4*)p;
            ar[2 * t + 1] = *(const float4*)(p + 4);
        }
    };
    auto sts_A = [&](int s, const float4* ar) {
#pragma unroll
        for (int t = 0; t < 4; t++) {
            int i = tid + t * 256;
            int row = i >> 3, seg = i & 7;
            uint32_t so = SWZ128((uint32_t)(row * 128 + seg * 16));
            uint4 hi, lo;
            split4(ar[2 * t],     hi.x, hi.y, lo.x, lo.y);
            split4(ar[2 * t + 1], hi.z, hi.w, lo.z, lo.w);
            *(uint4*)(smem + s * GSTAGE + so)         = hi;
            *(uint4*)(smem + s * GSTAGE + 16384 + so) = lo;
        }
    };

    const int wm = (warp & 3) * 32;
    const int wn = (warp >> 2) * 64;
    const int lr = lane & 7, g = lane >> 3;

    float acc[2][8][4];
#pragma unroll
    for (int i = 0; i < 2; i++)
#pragma unroll
        for (int j = 0; j < 8; j++)
#pragma unroll
            for (int q = 0; q < 4; q++) acc[i][j][q] = 0.0f;

    float4 areg[8];
    ldg_A(0, areg);
    load_B(0, 0);

    for (int kc = 0; kc < 8; kc++) {
        sts_A(kc & 1, areg);
        if (kc + 1 < 8) {
            ldg_A(kc + 1, areg);
            load_B(kc + 1, (kc + 1) & 1);
            asm volatile("cp.async.wait_group 1;" ::: "memory");
        } else {
            asm volatile("cp.async.wait_group 0;" ::: "memory");
        }
        __syncthreads();

        uint32_t sb = smb + (kc & 1) * GSTAGE;
#pragma unroll
        for (int ks = 0; ks < 4; ks++) {
            uint32_t ah[2][4], al[2][4];
#pragma unroll
            for (int am = 0; am < 2; am++) {
                int mrow = wm + am * 16 + (g & 1) * 8 + lr;
                int kb = ks * 16 + (g >> 1) * 8;
                uint32_t off = SWZ128((uint32_t)(mrow * 128 + kb * 2));
                ldsm_x4(ah[am], sb + off);
                ldsm_x4(al[am], sb + 16384 + off);
            }
            uint32_t bh[4][4], blf[4][4];
#pragma unroll
            for (int bb = 0; bb < 4; bb++) {
                int nrow = wn + bb * 16 + (g >> 1) * 8 + lr;
                int kb = ks * 16 + (g & 1) * 8;
                uint32_t off = SWZ128((uint32_t)(nrow * 128 + kb * 2));
                ldsm_x4(bh[bb],  sb + 32768 + off);
                ldsm_x4(blf[bb], sb + 49152 + off);
            }
#pragma unroll
            for (int am = 0; am < 2; am++)
#pragma unroll
                for (int bb = 0; bb < 4; bb++)
#pragma unroll
                    for (int h = 0; h < 2; h++) {
                        float* c = acc[am][bb * 2 + h];
                        mma16816(c, ah[am], &bh[bb][h * 2]);
                        mma16816(c, ah[am], &blf[bb][h * 2]);
                        mma16816(c, al[am], &bh[bb][h * 2]);
                    }
        }
        __syncthreads();
    }

    const int n_base = bn * 128 + wn;
#pragma unroll
    for (int am = 0; am < 2; am++) {
        int row = bm * 128 + wm + am * 16 + (lane >> 2);
#pragma unroll
        for (int b8 = 0; b8 < 8; b8++) {
            int n0 = n_base + b8 * 8 + (lane & 3) * 2;
            float bx = bias[n0], by = bias[n0 + 1];
            float* c = acc[am][b8];
            float2 v0 = make_float2(c[0] + bx, c[1] + by);
            float2 v1 = make_float2(c[2] + bx, c[3] + by);
            *(float2*)(g_xpre + (size_t)row * 512 + n0) = v0;
            *(float2*)(g_xpre + (size_t)(row + 8) * 512 + n0) = v1;
        }
    }
}

// ============================================================
// Kernel 2: persistent time scan v6 (lane-pair batch broadcast).
// 128 blocks x 256 threads, 2 batches/block.
// Thread t: unit jp = t>>1, batch bl = t&1. Lane PAIRS share the
// same unit -> identical weight addresses -> within-warp LDS
// broadcast (halves crossbar traffic vs v5).
// Thread computes all 4 gate cols of its (unit,batch) -> fused
// cell in regs, 1 barrier/step, parity-double-buffered h.
// Weights: k=0..39 in regs (4x20 ull), k=40..127 in smem.
// Warp skips rec loop only when BOTH batches are done (ballot).
// ============================================================
#define WSS 92                                   // smem weight stride (floats)
#define SC_W    0                                // [512 cols][92]
#define SC_H    (512 * WSS)                      // 2 parities x 2 batches x 132
#define SMEM2_FLOATS (SC_H + 2 * 2 * 132 + 32)
#define SMEM2_BYTES  (SMEM2_FLOATS * 4)

__global__ __launch_bounds__(256, 1)
void lstm_scan_kernel(const float* __restrict__ c0,
                      const float* __restrict__ h0,
                      const int* __restrict__ done,   // jnp.bool_ arrives as int32
                      const float* __restrict__ Wh,   // [128][512]
                      float* __restrict__ out)
{
    extern __shared__ float smemf[];
    float* wsm = smemf + SC_W;       // wsm[col*WSS + (k-40)], k=40..127
    float* hbb = smemf + SC_H;       // [par][bl][132]

    const int tid = threadIdx.x;
    const int blk = blockIdx.x;
    const int jp  = tid >> 1;                    // hidden unit (lane-pair shared)
    const int bl  = tid & 1;                     // batch lane 0/1
    const int bg  = blk * 2 + bl;                // global batch

    // --- fill smem weights: wsm[col][kp] = Wh[40+kp][col], kp=0..87 ---
    for (int i = tid; i < 88 * 512; i += 256) {
        int kp = i >> 9, col = i & 511;          // coalesced over col
        wsm[col * WSS + kp] = Wh[(40 + kp) * 512 + col];
    }

    // --- register weights: 4 cols x k=0..39 packed (shared by lane pair) ---
    ull wreg2[4][20];
#pragma unroll
    for (int c = 0; c < 4; c++) {
        const int col = jp + 128 * c;
#pragma unroll
        for (int k = 0; k < 40; k += 2)
            wreg2[c][k >> 1] = fpack2(Wh[k * 512 + col], Wh[(k + 1) * 512 + col]);
    }

    // --- init h parity buffer 0 (every thread writes its own (bl,jp)) ---
    hbb[0 * 264 + bl * 132 + jp] = h0[bg * 128 + jp];

    float c_reg = c0[bg * 128 + jp];
    float hlast = 0.0f;

    __syncthreads();

    // --- prefetch t = 0 ---
    float x0, x1, x2, x3;
    int dv;
    {
        const float* xp = g_xpre + (size_t)bg * 512;
        x0 = xp[jp]; x1 = xp[128 + jp]; x2 = xp[256 + jp]; x3 = xp[384 + jp];
        dv = done[bg];
    }

    for (int t = 0; t < T_STEPS; t++) {
        // prefetch t+1
        float nx0 = 0.f, nx1 = 0.f, nx2 = 0.f, nx3 = 0.f;
        int ndv = 0;
        if (t + 1 < T_STEPS) {
            const float* xp = g_xpre + ((size_t)(t + 1) * BATCH + bg) * 512;
            nx0 = xp[jp]; nx1 = xp[128 + jp]; nx2 = xp[256 + jp]; nx3 = xp[384 + jp];
            ndv = done[(t + 1) * BATCH + bg];
        }

        const float* hb = hbb + (t & 1) * 264 + bl * 132;   // read buffer (own batch)
        const float keep = dv ? 0.0f : 1.0f;
        float r0 = 0.f, r1 = 0.f, r2 = 0.f, r3 = 0.f;

        // warp-uniform skip: only when BOTH batches in this warp are done
        unsigned act = __ballot_sync(0xFFFFFFFFu, dv == 0);
        if (act) {
            ull a0 = 0, a1 = 0, a2 = 0, a3 = 0;
#pragma unroll
            for (int k = 0; k < 40; k += 4) {
                ulonglong2 hv = *(const ulonglong2*)&hb[k];
                a0 = ffma2(hv.x, wreg2[0][k >> 1], a0);
                a1 = ffma2(hv.x, wreg2[1][k >> 1], a1);
                a2 = ffma2(hv.x, wreg2[2][k >> 1], a2);
                a3 = ffma2(hv.x, wreg2[3][k >> 1], a3);
                a0 = ffma2(hv.y, wreg2[0][(k >> 1) + 1], a0);
                a1 = ffma2(hv.y, wreg2[1][(k >> 1) + 1], a1);
                a2 = ffma2(hv.y, wreg2[2][(k >> 1) + 1], a2);
                a3 = ffma2(hv.y, wreg2[3][(k >> 1) + 1], a3);
            }
#pragma unroll
            for (int k = 40; k < 128; k += 4) {
                ulonglong2 hv = *(const ulonglong2*)&hb[k];
                ulonglong2 w0 = *(const ulonglong2*)&wsm[(jp      ) * WSS + (k - 40)];
                ulonglong2 w1 = *(const ulonglong2*)&wsm[(jp + 128) * WSS + (k - 40)];
                ulonglong2 w2 = *(const ulonglong2*)&wsm[(jp + 256) * WSS + (k - 40)];
                ulonglong2 w3 = *(const ulonglong2*)&wsm[(jp + 384) * WSS + (k - 40)];
                a0 = ffma2(hv.x, w0.x, a0);
                a1 = ffma2(hv.x, w1.x, a1);
                a2 = ffma2(hv.x, w2.x, a2);
                a3 = ffma2(hv.x, w3.x, a3);
                a0 = ffma2(hv.y, w0.y, a0);
                a1 = ffma2(hv.y, w1.y, a1);
                a2 = ffma2(hv.y, w2.y, a2);
                a3 = ffma2(hv.y, w3.y, a3);
            }
            r0 = funpack_add(a0);
            r1 = funpack_add(a1);
            r2 = funpack_add(a2);
            r3 = funpack_add(a3);
        }

        // gates = xpre + keep * rec  (per-batch reset stays algebraic)
        float gi = fmaf(keep, r0, x0);
        float gf = fmaf(keep, r1, x1);
        float gg = fmaf(keep, r2, x2);
        float go = fmaf(keep, r3, x3);

        // --- fused LSTM cell ---
        float cprev = keep * c_reg;
        float nc = sigm_(gf) * cprev + sigm_(gi) * tanh_(gg);
        float nh = sigm_(go) * tanh_(nc);
        c_reg = nc;
        hlast = nh;
        out[(size_t)(t * BATCH + bg) * 128 + jp] = nh;
        hbb[((t + 1) & 1) * 264 + bl * 132 + jp] = nh;   // write other parity

        __syncthreads();

        x0 = nx0; x1 = nx1; x2 = nx2; x3 = nx3;
        dv = ndv;
    }

    // finals: cT then hT after ys
    out[(size_t)YS_ELEMS + bg * 128 + jp] = c_reg;
    out[(size_t)YS_ELEMS + BATCH * HID + bg * 128 + jp] = hlast;
}

// ============================================================
extern "C" void kernel_launch(void* const* d_in, const int* in_sizes, int n_in,
                              void* d_out, int out_size)
{
    const float* c0   = (const float*)d_in[0];
    const float* h0   = (const float*)d_in[1];
    const float* obs  = (const float*)d_in[2];
    const int*   done = (const int*)d_in[3];       // jnp.bool_ -> int32
    const float* Wi   = (const float*)d_in[4];
    const float* Wh   = (const float*)d_in[5];
    const float* bias = (const float*)d_in[6];
    float* out = (float*)d_out;

    cudaFuncSetAttribute(gemm_hmma_kernel,
                         cudaFuncAttributeMaxDynamicSharedMemorySize, GSM_TOTAL);
    cudaFuncSetAttribute(lstm_scan_kernel,
                         cudaFuncAttributeMaxDynamicSharedMemorySize, SMEM2_BYTES);

    split_wiT_kernel<<<1024, 256>>>(Wi);
    dim3 gg(4, 1024);
    gemm_hmma_kernel<<<gg, 256, GSM_TOTAL>>>(obs, bias);
    lstm_scan_kernel<<<128, 256, SMEM2_BYTES>>>(c0, h0, done, Wh, out);
}